// round 2
// baseline (speedup 1.0000x reference)
#include <cuda_runtime.h>
#include <cstdint>

#define NMAX 50000
#define FD   128

__device__ float g_agg1[NMAX * FD];
__device__ float g_x1  [NMAX * FD];
__device__ float g_agg2[NMAX * FD];
__device__ float g_cnt [NMAX];
__device__ float g_inv [NMAX];

__global__ void zero_kernel(int n_feat, int n_nodes) {
    int i = blockIdx.x * blockDim.x + threadIdx.x;
    int stride = gridDim.x * blockDim.x;
    int total = n_feat + n_nodes;
    for (int idx = i; idx < total; idx += stride) {
        if (idx < n_feat) {
            g_agg1[idx] = 0.0f;
            g_agg2[idx] = 0.0f;
        } else {
            g_cnt[idx - n_feat] = 0.0f;
        }
    }
}

__global__ void count_kernel(const int* __restrict__ dst, int E, int n) {
    int e = blockIdx.x * blockDim.x + threadIdx.x;
    if (e < E) {
        int d = dst[e];
        if ((unsigned)d < (unsigned)n) atomicAdd(&g_cnt[d], 1.0f);
    }
}

__global__ void inv_kernel(int n) {
    int i = blockIdx.x * blockDim.x + threadIdx.x;
    if (i < n) g_inv[i] = 1.0f / fmaxf(g_cnt[i], 1.0f);
}

// one warp per edge; 128B vectorized reduction per lane group
__global__ void scatter_kernel(const float* __restrict__ feat,
                               const int* __restrict__ src,
                               const int* __restrict__ dst,
                               float* __restrict__ agg, int E, int n) {
    int gt   = blockIdx.x * blockDim.x + threadIdx.x;
    int e    = gt >> 5;
    int lane = gt & 31;
    if (e >= E) return;
    int s = src[e];
    int d = dst[e];
    if ((unsigned)s >= (unsigned)n || (unsigned)d >= (unsigned)n) return;
    float4 v = __ldg(((const float4*)(feat + (size_t)s * FD)) + lane);
    float* out = agg + (size_t)d * FD + (size_t)lane * 4;
    asm volatile("red.global.add.v4.f32 [%0], {%1,%2,%3,%4};"
                 :: "l"(out), "f"(v.x), "f"(v.y), "f"(v.z), "f"(v.w)
                 : "memory");
}

// C[n][128] = act( (A*inv[row]) @ Wl^T + B @ Wr^T + bias )
// BM=64, BN=128, BK=32, 128 threads, 8x8 per-thread tile
template <bool RELU>
__global__ void gemm_dual_kernel(const float* __restrict__ A,
                                 const float* __restrict__ B,
                                 const float* __restrict__ Wl,
                                 const float* __restrict__ Wr,
                                 const float* __restrict__ bias,
                                 float* __restrict__ C, int n) {
    const int BM = 64;
    const int BK = 32;

    __shared__ __align__(16) float As[BK][BM];
    __shared__ __align__(16) float Ws[BK][128];
    __shared__ float Sinv[BM];

    int t = threadIdx.x;
    int block_row = blockIdx.x * BM;

    if (t < BM) {
        int r = block_row + t;
        Sinv[t] = (r < n) ? g_inv[r] : 0.0f;
    }

    float acc[8][8];
#pragma unroll
    for (int i = 0; i < 8; i++)
#pragma unroll
        for (int j = 0; j < 8; j++) acc[i][j] = 0.0f;

    int row0 = (t >> 4) * 8;
    int col0 = (t & 15) * 8;

    for (int kc = 0; kc < 256; kc += BK) {
        bool isA = (kc < 128);
        const float* Aptr = isA ? A : B;
        const float* Wptr = isA ? Wl : Wr;
        int kbase = isA ? kc : (kc - 128);

        __syncthreads();

#pragma unroll
        for (int i = 0; i < 4; i++) {
            int f   = i * 128 + t;
            int row = f >> 3;
            int kq  = (f & 7) * 4;
            int gr  = block_row + row;
            float4 v = make_float4(0.f, 0.f, 0.f, 0.f);
            if (gr < n)
                v = __ldg((const float4*)(Aptr + (size_t)gr * FD + kbase + kq));
            if (isA) {
                float s = Sinv[row];
                v.x *= s; v.y *= s; v.z *= s; v.w *= s;
            }
            As[kq + 0][row] = v.x;
            As[kq + 1][row] = v.y;
            As[kq + 2][row] = v.z;
            As[kq + 3][row] = v.w;
        }
#pragma unroll
        for (int i = 0; i < 8; i++) {
            int f   = i * 128 + t;
            int out = f >> 3;
            int kq  = (f & 7) * 4;
            float4 v = __ldg((const float4*)(Wptr + (size_t)out * FD + kbase + kq));
            Ws[kq + 0][out] = v.x;
            Ws[kq + 1][out] = v.y;
            Ws[kq + 2][out] = v.z;
            Ws[kq + 3][out] = v.w;
        }
        __syncthreads();

#pragma unroll
        for (int k = 0; k < BK; k++) {
            float4 a0 = *(const float4*)&As[k][row0];
            float4 a1 = *(const float4*)&As[k][row0 + 4];
            float4 w0 = *(const float4*)&Ws[k][col0];
            float4 w1 = *(const float4*)&Ws[k][col0 + 4];
            float a[8] = {a0.x, a0.y, a0.z, a0.w, a1.x, a1.y, a1.z, a1.w};
            float w[8] = {w0.x, w0.y, w0.z, w0.w, w1.x, w1.y, w1.z, w1.w};
#pragma unroll
            for (int i = 0; i < 8; i++)
#pragma unroll
                for (int j = 0; j < 8; j++)
                    acc[i][j] = fmaf(a[i], w[j], acc[i][j]);
        }
    }

    float bb[8];
#pragma unroll
    for (int j = 0; j < 8; j++) bb[j] = __ldg(&bias[col0 + j]);

#pragma unroll
    for (int i = 0; i < 8; i++) {
        int gr = block_row + row0 + i;
        if (gr < n) {
#pragma unroll
            for (int j = 0; j < 8; j += 4) {
                float4 o;
                o.x = acc[i][j + 0] + bb[j + 0];
                o.y = acc[i][j + 1] + bb[j + 1];
                o.z = acc[i][j + 2] + bb[j + 2];
                o.w = acc[i][j + 3] + bb[j + 3];
                if (RELU) {
                    o.x = fmaxf(o.x, 0.f);
                    o.y = fmaxf(o.y, 0.f);
                    o.z = fmaxf(o.z, 0.f);
                    o.w = fmaxf(o.w, 0.f);
                }
                *(float4*)&C[(size_t)gr * FD + col0 + j] = o;
            }
        }
    }
}

extern "C" void kernel_launch(void* const* d_in, const int* in_sizes, int n_in,
                              void* d_out, int out_size) {
    const float* x   = (const float*)d_in[0];
    const int*   ei  = (const int*)d_in[1];    // int32: JAX downgrades int64 without x64
    const float* W1l = (const float*)d_in[2];
    const float* b1l = (const float*)d_in[3];
    const float* W1r = (const float*)d_in[4];
    const float* W2l = (const float*)d_in[5];
    const float* b2l = (const float*)d_in[6];
    const float* W2r = (const float*)d_in[7];
    const float* W3l = (const float*)d_in[8];
    const float* b3l = (const float*)d_in[9];
    const float* W3r = (const float*)d_in[10];

    int n = in_sizes[0] / FD;
    int E = in_sizes[1] / 2;
    const int* src = ei;
    const int* dst = ei + E;

    float* out_h1 = (float*)d_out;
    float* out_h2 = (float*)d_out + (size_t)n * FD;

    void *p_agg1 = nullptr, *p_agg2 = nullptr, *p_x1 = nullptr;
    cudaGetSymbolAddress(&p_agg1, g_agg1);
    cudaGetSymbolAddress(&p_agg2, g_agg2);
    cudaGetSymbolAddress(&p_x1,   g_x1);
    float* agg1 = (float*)p_agg1;
    float* agg2 = (float*)p_agg2;
    float* x1   = (float*)p_x1;

    int feat_total = n * FD;
    long long sthreads = (long long)E * 32;
    int sblocks = (int)((sthreads + 255) / 256);
    int gblocks = (n + 63) / 64;

    zero_kernel<<<2048, 256>>>(feat_total, n);
    count_kernel<<<(E + 255) / 256, 256>>>(dst, E, n);
    inv_kernel<<<(n + 255) / 256, 256>>>(n);

    scatter_kernel<<<sblocks, 256>>>(x, src, dst, agg1, E, n);
    gemm_dual_kernel<true><<<gblocks, 128>>>(agg1, x, W1l, W1r, b1l, x1, n);

    scatter_kernel<<<sblocks, 256>>>(x1, src, dst, agg2, E, n);
    gemm_dual_kernel<false><<<gblocks, 128>>>(agg2, x1, W2l, W2r, b2l, out_h1, n);
    gemm_dual_kernel<false><<<gblocks, 128>>>(agg2, x1, W3l, W3r, b3l, out_h2, n);
}

// round 4
// speedup vs baseline: 1.3306x; 1.3306x over previous
#include <cuda_runtime.h>
#include <cuda_bf16.h>
#include <cstdint>

#define NMAX 50000
#define NPAD 50176
#define FD   128

// ---------------- scratch (device globals) ---------------------------------
__device__ float g_agg1[NMAX * FD];
__device__ float g_x1  [NMAX * FD];
__device__ float g_agg2[NMAX * FD];
__device__ float g_cnt [NMAX];
__device__ float g_inv [NMAX];
// bf16 split A-concat rows: [agg*inv (cols 0-127) | self (cols 128-255)]
__device__ __nv_bfloat16 g_a1h[(size_t)NPAD * 256];
__device__ __nv_bfloat16 g_a1l[(size_t)NPAD * 256];
__device__ __nv_bfloat16 g_a2h[(size_t)NPAD * 256];
__device__ __nv_bfloat16 g_a2l[(size_t)NPAD * 256];
// weights: 3 layers x [128 out x 256 k]  (k = [Wl | Wr])
__device__ __nv_bfloat16 g_wh[3 * 128 * 256];
__device__ __nv_bfloat16 g_wl[3 * 128 * 256];

// ---------------- small kernels --------------------------------------------
__global__ void zero_kernel(int n_feat, int n_nodes) {
    int i = blockIdx.x * blockDim.x + threadIdx.x;
    int stride = gridDim.x * blockDim.x;
    int total = n_feat + n_nodes;
    for (int idx = i; idx < total; idx += stride) {
        if (idx < n_feat) { g_agg1[idx] = 0.0f; g_agg2[idx] = 0.0f; }
        else g_cnt[idx - n_feat] = 0.0f;
    }
}

__global__ void count_kernel(const int* __restrict__ dst, int E, int n) {
    int e = blockIdx.x * blockDim.x + threadIdx.x;
    if (e < E) {
        int d = dst[e];
        if ((unsigned)d < (unsigned)n) atomicAdd(&g_cnt[d], 1.0f);
    }
}

__global__ void inv_kernel(int n) {
    int i = blockIdx.x * blockDim.x + threadIdx.x;
    if (i < n) g_inv[i] = 1.0f / fmaxf(g_cnt[i], 1.0f);
}

__global__ void scatter_kernel(const float* __restrict__ feat,
                               const int* __restrict__ src,
                               const int* __restrict__ dst,
                               float* __restrict__ agg, int E, int n) {
    int gt = blockIdx.x * blockDim.x + threadIdx.x;
    int e = gt >> 5, lane = gt & 31;
    if (e >= E) return;
    int s = src[e], d = dst[e];
    if ((unsigned)s >= (unsigned)n || (unsigned)d >= (unsigned)n) return;
    float4 v = __ldg(((const float4*)(feat + (size_t)s * FD)) + lane);
    float* out = agg + (size_t)d * FD + (size_t)lane * 4;
    asm volatile("red.global.add.v4.f32 [%0], {%1,%2,%3,%4};"
                 :: "l"(out), "f"(v.x), "f"(v.y), "f"(v.z), "f"(v.w) : "memory");
}

__device__ __forceinline__ void split_store(float v, __nv_bfloat16* h, __nv_bfloat16* l) {
    __nv_bfloat16 hb = __float2bfloat16(v);
    *h = hb;
    *l = __float2bfloat16(v - __bfloat162float(hb));
}

// fp32 [n x 128] (optional row scale) -> bf16 hi/lo at [row*256 + colbase]
__global__ void conv_feat(const float* __restrict__ src, const float* __restrict__ scale,
                          __nv_bfloat16* __restrict__ dh, __nv_bfloat16* __restrict__ dl,
                          int colbase, int n) {
    int q = blockIdx.x * blockDim.x + threadIdx.x;
    if (q >= n * 32) return;
    int row = q >> 5, c4 = (q & 31) << 2;
    float4 v = __ldg((const float4*)(src + (size_t)row * FD + c4));
    if (scale) {
        float s = __ldg(scale + row);
        v.x *= s; v.y *= s; v.z *= s; v.w *= s;
    }
    size_t o = (size_t)row * 256 + colbase + c4;
    split_store(v.x, dh + o + 0, dl + o + 0);
    split_store(v.y, dh + o + 1, dl + o + 1);
    split_store(v.z, dh + o + 2, dl + o + 2);
    split_store(v.w, dh + o + 3, dl + o + 3);
}

__global__ void conv_w(const float* W1l, const float* W1r,
                       const float* W2l, const float* W2r,
                       const float* W3l, const float* W3r) {
    int q = blockIdx.x * blockDim.x + threadIdx.x;
    if (q >= 3 * 128 * 64) return;
    int L = q / 8192, rem = q % 8192;
    int o = rem >> 6, kq = (rem & 63) << 2;
    const float* Wl = (L == 0) ? W1l : (L == 1) ? W2l : W3l;
    const float* Wr = (L == 0) ? W1r : (L == 1) ? W2r : W3r;
    const float* sp = (kq < 128) ? (Wl + o * 128 + kq) : (Wr + o * 128 + kq - 128);
    float4 v = __ldg((const float4*)sp);
    size_t out = (size_t)L * 32768 + (size_t)o * 256 + kq;
    split_store(v.x, g_wh + out + 0, g_wl + out + 0);
    split_store(v.y, g_wh + out + 1, g_wl + out + 1);
    split_store(v.z, g_wh + out + 2, g_wl + out + 2);
    split_store(v.w, g_wh + out + 3, g_wl + out + 3);
}

// ---------------- mma.sync bf16 GEMM ---------------------------------------
// C[128x128] per CTA = Acat[128x256] @ W^T[256x128], split hi*hi+hi*lo+lo*hi.
// smem: padded stride 272B per 128-wide bf16 row (conflict-free ldmatrix).
#define PS   136                  // padded row stride in bf16 elems (272B)
#define BUFB (128 * PS * 2)       // 34816 bytes per buffer
#define OFF_AH 0
#define OFF_AL (BUFB)
#define OFF_WH (2 * BUFB)
#define OFF_WL (3 * BUFB)
#define SMEM_TOTAL (4 * BUFB)     // 139264

__device__ __forceinline__ uint32_t smem_u32(const void* p) {
    uint32_t a;
    asm("{ .reg .u64 t; cvta.to.shared.u64 t, %1; cvt.u32.u64 %0, t; }" : "=r"(a) : "l"(p));
    return a;
}

__device__ __forceinline__ void ldm_x4(uint32_t* r, uint32_t addr) {
    asm volatile("ldmatrix.sync.aligned.m8n8.x4.shared.b16 {%0,%1,%2,%3}, [%4];"
                 : "=r"(r[0]), "=r"(r[1]), "=r"(r[2]), "=r"(r[3]) : "r"(addr));
}

__device__ __forceinline__ void mma_bf16(float* d, const uint32_t* a, const uint32_t* b) {
    asm volatile("mma.sync.aligned.m16n8k16.row.col.f32.bf16.bf16.f32 "
                 "{%0,%1,%2,%3}, {%4,%5,%6,%7}, {%8,%9}, {%0,%1,%2,%3};"
                 : "+f"(d[0]), "+f"(d[1]), "+f"(d[2]), "+f"(d[3])
                 : "r"(a[0]), "r"(a[1]), "r"(a[2]), "r"(a[3]), "r"(b[0]), "r"(b[1]));
}

template <bool WRITE_SPLIT>
__global__ void __launch_bounds__(256, 1)
gemm_mma(const __nv_bfloat16* __restrict__ Ahi, const __nv_bfloat16* __restrict__ Alo,
         const __nv_bfloat16* __restrict__ Whi, const __nv_bfloat16* __restrict__ Wlo,
         const float* __restrict__ bias, float* __restrict__ outF,
         __nv_bfloat16* __restrict__ sph, __nv_bfloat16* __restrict__ spl, int n) {
    extern __shared__ __align__(16) char smem[];
    uint32_t sb = smem_u32(smem);
    int tid = threadIdx.x, wid = tid >> 5, lane = tid & 31;
    int base_row = blockIdx.x * 128;

    int m_warp = (wid & 3) * 32;       // warp tile: 32 rows x 64 cols
    int n_warp = (wid >> 2) * 64;

    float acc[2][8][4];
#pragma unroll
    for (int i = 0; i < 2; i++)
#pragma unroll
        for (int j = 0; j < 8; j++)
#pragma unroll
            for (int k = 0; k < 4; k++) acc[i][j][k] = 0.0f;

    // ldmatrix lane addressing (byte offsets within a buffer)
    int g  = lane >> 3, lr = lane & 7;
    // A x4 (m16k16): rows m0..15, cols 2 halves of 8
    int a_row = (g & 1) * 8 + lr;
    int a_col = (g >> 1) * 8;
    // B x4 (two n8 tiles x k16): g0: n+lr k0 | g1: n+8+lr k0 | g2: n+lr k8 | g3: n+8+lr k8
    int b_row = (g & 1) * 8 + lr;
    int b_col = (g >> 1) * 8;

    for (int kc = 0; kc < 2; kc++) {
        // ---- load tiles: A[128x128] hi/lo, W[128x128] hi/lo --------------
        if (kc) __syncthreads();
#pragma unroll
        for (int i = 0; i < 8; i++) {
            int q = tid + i * 256;            // 0..2047 uint4 slots
            int row = q >> 4;                 // 16 uint4 per row
            int c8 = (q & 15) * 8;            // bf16 col
            size_t gA = (size_t)(base_row + row) * 256 + kc * 128 + c8;
            size_t gW = (size_t)row * 256 + kc * 128 + c8;
            uint32_t so = (uint32_t)(row * PS + c8) * 2;
            *(uint4*)(smem + OFF_AH + so) = *(const uint4*)(Ahi + gA);
            *(uint4*)(smem + OFF_AL + so) = *(const uint4*)(Alo + gA);
            *(uint4*)(smem + OFF_WH + so) = *(const uint4*)(Whi + gW);
            *(uint4*)(smem + OFF_WL + so) = *(const uint4*)(Wlo + gW);
        }
        __syncthreads();

        // ---- compute ------------------------------------------------------
#pragma unroll
        for (int k16 = 0; k16 < 8; k16++) {
            int kb = k16 * 16;
            uint32_t ah[2][4], al[2][4];
#pragma unroll
            for (int mi = 0; mi < 2; mi++) {
                uint32_t ad = sb + (uint32_t)((m_warp + mi * 16 + a_row) * PS + kb + a_col) * 2;
                ldm_x4(ah[mi], OFF_AH + ad);
                ldm_x4(al[mi], OFF_AL + ad);
            }
            uint32_t bh[8][2], bl[8][2];
#pragma unroll
            for (int np = 0; np < 4; np++) {   // pairs of n-tiles
                uint32_t bd = sb + (uint32_t)((n_warp + np * 16 + b_row) * PS + kb + b_col) * 2;
                uint32_t t[4];
                ldm_x4(t, OFF_WH + bd);
                bh[np * 2 + 0][0] = t[0]; bh[np * 2 + 0][1] = t[2];
                bh[np * 2 + 1][0] = t[1]; bh[np * 2 + 1][1] = t[3];
                ldm_x4(t, OFF_WL + bd);
                bl[np * 2 + 0][0] = t[0]; bl[np * 2 + 0][1] = t[2];
                bl[np * 2 + 1][0] = t[1]; bl[np * 2 + 1][1] = t[3];
            }
#pragma unroll
            for (int mi = 0; mi < 2; mi++)
#pragma unroll
                for (int ni = 0; ni < 8; ni++) {
                    mma_bf16(acc[mi][ni], ah[mi], bh[ni]);
                    mma_bf16(acc[mi][ni], ah[mi], bl[ni]);
                    mma_bf16(acc[mi][ni], al[mi], bh[ni]);
                }
        }
    }

    // ---- epilogue ----------------------------------------------------------
    int r_in = lane >> 2;          // 0..7
    int c_in = (lane & 3) * 2;     // 0,2,4,6
#pragma unroll
    for (int mi = 0; mi < 2; mi++) {
#pragma unroll
        for (int half = 0; half < 2; half++) {   // c0/c1 vs c2/c3 (rows +0/+8)
            int gr = base_row + m_warp + mi * 16 + r_in + half * 8;
            if (gr >= n) continue;
#pragma unroll
            for (int ni = 0; ni < 8; ni++) {
                int col = n_warp + ni * 8 + c_in;
                float y0 = acc[mi][ni][half * 2 + 0] + __ldg(bias + col + 0);
                float y1 = acc[mi][ni][half * 2 + 1] + __ldg(bias + col + 1);
                if (WRITE_SPLIT) { y0 = fmaxf(y0, 0.f); y1 = fmaxf(y1, 0.f); }
                *(float2*)(outF + (size_t)gr * FD + col) = make_float2(y0, y1);
                if (WRITE_SPLIT) {
                    size_t so = (size_t)gr * 256 + 128 + col;
                    split_store(y0, sph + so + 0, spl + so + 0);
                    split_store(y1, sph + so + 1, spl + so + 1);
                }
            }
        }
    }
}

// ---------------- launch ----------------------------------------------------
extern "C" void kernel_launch(void* const* d_in, const int* in_sizes, int n_in,
                              void* d_out, int out_size) {
    const float* x   = (const float*)d_in[0];
    const int*   ei  = (const int*)d_in[1];
    const float* W1l = (const float*)d_in[2];
    const float* b1l = (const float*)d_in[3];
    const float* W1r = (const float*)d_in[4];
    const float* W2l = (const float*)d_in[5];
    const float* b2l = (const float*)d_in[6];
    const float* W2r = (const float*)d_in[7];
    const float* W3l = (const float*)d_in[8];
    const float* b3l = (const float*)d_in[9];
    const float* W3r = (const float*)d_in[10];

    int n = in_sizes[0] / FD;
    int E = in_sizes[1] / 2;
    const int* src = ei;
    const int* dst = ei + E;

    float* out_h1 = (float*)d_out;
    float* out_h2 = (float*)d_out + (size_t)n * FD;

    void *pa1 = 0, *pa2 = 0, *px1 = 0, *pinv = 0;
    void *pa1h = 0, *pa1l = 0, *pa2h = 0, *pa2l = 0, *pwh = 0, *pwl = 0;
    cudaGetSymbolAddress(&pa1, g_agg1);
    cudaGetSymbolAddress(&pa2, g_agg2);
    cudaGetSymbolAddress(&px1, g_x1);
    cudaGetSymbolAddress(&pinv, g_inv);
    cudaGetSymbolAddress(&pa1h, g_a1h);
    cudaGetSymbolAddress(&pa1l, g_a1l);
    cudaGetSymbolAddress(&pa2h, g_a2h);
    cudaGetSymbolAddress(&pa2l, g_a2l);
    cudaGetSymbolAddress(&pwh, g_wh);
    cudaGetSymbolAddress(&pwl, g_wl);
    float* agg1 = (float*)pa1;
    float* agg2 = (float*)pa2;
    float* x1   = (float*)px1;
    float* inv  = (float*)pinv;
    __nv_bfloat16* a1h = (__nv_bfloat16*)pa1h;
    __nv_bfloat16* a1l = (__nv_bfloat16*)pa1l;
    __nv_bfloat16* a2h = (__nv_bfloat16*)pa2h;
    __nv_bfloat16* a2l = (__nv_bfloat16*)pa2l;
    __nv_bfloat16* wh  = (__nv_bfloat16*)pwh;
    __nv_bfloat16* wl  = (__nv_bfloat16*)pwl;

    cudaFuncSetAttribute(gemm_mma<true>,  cudaFuncAttributeMaxDynamicSharedMemorySize, SMEM_TOTAL);
    cudaFuncSetAttribute(gemm_mma<false>, cudaFuncAttributeMaxDynamicSharedMemorySize, SMEM_TOTAL);

    int feat_total = n * FD;
    long long sthreads = (long long)E * 32;
    int sblocks = (int)((sthreads + 255) / 256);
    int cblocks = (n * 32 + 255) / 256;
    int gblocks = (n + 127) / 128;

    zero_kernel<<<2048, 256>>>(feat_total, n);
    count_kernel<<<(E + 255) / 256, 256>>>(dst, E, n);
    inv_kernel<<<(n + 255) / 256, 256>>>(n);

    conv_w<<<(3 * 128 * 64 + 255) / 256, 256>>>(W1l, W1r, W2l, W2r, W3l, W3r);
    conv_feat<<<cblocks, 256>>>(x, nullptr, a1h, a1l, 128, n);      // self part, layer 1

    scatter_kernel<<<sblocks, 256>>>(x, src, dst, agg1, E, n);
    conv_feat<<<cblocks, 256>>>(agg1, inv, a1h, a1l, 0, n);         // agg part, layer 1

    gemm_mma<true><<<gblocks, 256, SMEM_TOTAL>>>(a1h, a1l, wh, wl, b1l,
                                                 x1, a2h, a2l, n);

    scatter_kernel<<<sblocks, 256>>>(x1, src, dst, agg2, E, n);
    conv_feat<<<cblocks, 256>>>(agg2, inv, a2h, a2l, 0, n);         // agg part, layers 2/3

    gemm_mma<false><<<gblocks, 256, SMEM_TOTAL>>>(a2h, a2l, wh + 32768, wl + 32768, b2l,
                                                  out_h1, nullptr, nullptr, n);
    gemm_mma<false><<<gblocks, 256, SMEM_TOTAL>>>(a2h, a2l, wh + 65536, wl + 65536, b3l,
                                                  out_h2, nullptr, nullptr, n);
}

// round 5
// speedup vs baseline: 1.7793x; 1.3371x over previous
#include <cuda_runtime.h>
#include <cuda_bf16.h>
#include <cstdint>

#define NMAX 50000
#define FD   128

// ---------------- scratch (device globals) ---------------------------------
__device__ float g_agg1[NMAX * FD];
__device__ float g_x1  [NMAX * FD];
__device__ float g_agg2[NMAX * FD];
__device__ float g_cnt [NMAX];
__device__ float g_inv [NMAX];
// weights: 3 layers x [128 out x 256 k]  (k = [Wl | Wr]), bf16 hi/lo split
__device__ __nv_bfloat16 g_wh[3 * 128 * 256];
__device__ __nv_bfloat16 g_wl[3 * 128 * 256];

// ---------------- small kernels --------------------------------------------
__global__ void zero_kernel(int n_feat, int n_nodes) {
    int i = blockIdx.x * blockDim.x + threadIdx.x;
    int stride = gridDim.x * blockDim.x;
    int total = n_feat + n_nodes;
    for (int idx = i; idx < total; idx += stride) {
        if (idx < n_feat) { g_agg1[idx] = 0.0f; g_agg2[idx] = 0.0f; }
        else g_cnt[idx - n_feat] = 0.0f;
    }
}

__global__ void count_kernel(const int* __restrict__ dst, int E, int n) {
    int e = blockIdx.x * blockDim.x + threadIdx.x;
    if (e < E) {
        int d = dst[e];
        if ((unsigned)d < (unsigned)n) atomicAdd(&g_cnt[d], 1.0f);
    }
}

__global__ void inv_kernel(int n) {
    int i = blockIdx.x * blockDim.x + threadIdx.x;
    if (i < n) g_inv[i] = 1.0f / fmaxf(g_cnt[i], 1.0f);
}

// 4 edges per warp: indices via one broadcast int4 load, then 4 independent
// LDG.128 (MLP=4) followed by 4 RED.v4.
__global__ void scatter_kernel(const float* __restrict__ feat,
                               const int* __restrict__ src,
                               const int* __restrict__ dst,
                               float* __restrict__ agg, int E, int n) {
    int gt = blockIdx.x * blockDim.x + threadIdx.x;
    int warp = gt >> 5, lane = gt & 31;
    int e0 = warp * 4;
    if (e0 >= E) return;

    int ss[4], dd[4];
    if (e0 + 4 <= E) {
        int4 sv = __ldg((const int4*)(src + e0));
        int4 dv = __ldg((const int4*)(dst + e0));
        ss[0] = sv.x; ss[1] = sv.y; ss[2] = sv.z; ss[3] = sv.w;
        dd[0] = dv.x; dd[1] = dv.y; dd[2] = dv.z; dd[3] = dv.w;
    } else {
#pragma unroll
        for (int i = 0; i < 4; i++) {
            int e = e0 + i;
            ss[i] = (e < E) ? __ldg(src + e) : -1;
            dd[i] = (e < E) ? __ldg(dst + e) : -1;
        }
    }

    bool ok[4];
    float4 v[4];
#pragma unroll
    for (int i = 0; i < 4; i++) {
        ok[i] = (unsigned)ss[i] < (unsigned)n && (unsigned)dd[i] < (unsigned)n;
        v[i] = ok[i] ? __ldg(((const float4*)(feat + (size_t)ss[i] * FD)) + lane)
                     : make_float4(0.f, 0.f, 0.f, 0.f);
    }
#pragma unroll
    for (int i = 0; i < 4; i++) {
        if (ok[i]) {
            float* out = agg + (size_t)dd[i] * FD + (size_t)lane * 4;
            asm volatile("red.global.add.v4.f32 [%0], {%1,%2,%3,%4};"
                         :: "l"(out), "f"(v[i].x), "f"(v[i].y), "f"(v[i].z), "f"(v[i].w)
                         : "memory");
        }
    }
}

__device__ __forceinline__ void split2(float a, float b, uint32_t& hi, uint32_t& lo) {
    __nv_bfloat16 ah = __float2bfloat16(a);
    __nv_bfloat16 bh = __float2bfloat16(b);
    __nv_bfloat162 h2 = __nv_bfloat162(ah, bh);
    __nv_bfloat162 l2 = __nv_bfloat162(__float2bfloat16(a - __bfloat162float(ah)),
                                       __float2bfloat16(b - __bfloat162float(bh)));
    hi = *(uint32_t*)&h2;
    lo = *(uint32_t*)&l2;
}

__device__ __forceinline__ void split_store(float v, __nv_bfloat16* h, __nv_bfloat16* l) {
    __nv_bfloat16 hb = __float2bfloat16(v);
    *h = hb;
    *l = __float2bfloat16(v - __bfloat162float(hb));
}

__global__ void conv_w(const float* W1l, const float* W1r,
                       const float* W2l, const float* W2r,
                       const float* W3l, const float* W3r) {
    int q = blockIdx.x * blockDim.x + threadIdx.x;
    if (q >= 3 * 128 * 64) return;
    int L = q / 8192, rem = q % 8192;
    int o = rem >> 6, kq = (rem & 63) << 2;
    const float* Wl = (L == 0) ? W1l : (L == 1) ? W2l : W3l;
    const float* Wr = (L == 0) ? W1r : (L == 1) ? W2r : W3r;
    const float* sp = (kq < 128) ? (Wl + o * 128 + kq) : (Wr + o * 128 + kq - 128);
    float4 v = __ldg((const float4*)sp);
    size_t out = (size_t)L * 32768 + (size_t)o * 256 + kq;
    split_store(v.x, g_wh + out + 0, g_wl + out + 0);
    split_store(v.y, g_wh + out + 1, g_wl + out + 1);
    split_store(v.z, g_wh + out + 2, g_wl + out + 2);
    split_store(v.w, g_wh + out + 3, g_wl + out + 3);
}

// ---------------- mma.sync bf16 GEMM (fp32 inputs, in-register split) -------
// C[128x128] per CTA = [Aagg*inv | Aself][128x256] @ W^T[256x128]
// split: hi*hi + hi*lo + lo*hi, fp32 accumulate.
#define PS   136
#define BUFB (128 * PS * 2)
#define OFF_AH 0
#define OFF_AL (BUFB)
#define OFF_WH (2 * BUFB)
#define OFF_WL (3 * BUFB)
#define OFF_SINV (4 * BUFB)
#define SMEM_TOTAL (4 * BUFB + 512)

__device__ __forceinline__ uint32_t smem_u32(const void* p) {
    uint32_t a;
    asm("{ .reg .u64 t; cvta.to.shared.u64 t, %1; cvt.u32.u64 %0, t; }" : "=r"(a) : "l"(p));
    return a;
}

__device__ __forceinline__ void ldm_x4(uint32_t* r, uint32_t addr) {
    asm volatile("ldmatrix.sync.aligned.m8n8.x4.shared.b16 {%0,%1,%2,%3}, [%4];"
                 : "=r"(r[0]), "=r"(r[1]), "=r"(r[2]), "=r"(r[3]) : "r"(addr));
}

__device__ __forceinline__ void mma_bf16(float* d, const uint32_t* a, const uint32_t* b) {
    asm volatile("mma.sync.aligned.m16n8k16.row.col.f32.bf16.bf16.f32 "
                 "{%0,%1,%2,%3}, {%4,%5,%6,%7}, {%8,%9}, {%0,%1,%2,%3};"
                 : "+f"(d[0]), "+f"(d[1]), "+f"(d[2]), "+f"(d[3])
                 : "r"(a[0]), "r"(a[1]), "r"(a[2]), "r"(a[3]), "r"(b[0]), "r"(b[1]));
}

template <bool RELU>
__global__ void __launch_bounds__(256, 1)
gemm_mma(const float* __restrict__ Aagg, const float* __restrict__ scale,
         const float* __restrict__ Aself,
         const __nv_bfloat16* __restrict__ Whi, const __nv_bfloat16* __restrict__ Wlo,
         const float* __restrict__ bias, float* __restrict__ outF, int n) {
    extern __shared__ __align__(16) char smem[];
    uint32_t sb = smem_u32(smem);
    float* Sinv = (float*)(smem + OFF_SINV);
    int tid = threadIdx.x, wid = tid >> 5, lane = tid & 31;
    int base_row = blockIdx.x * 128;

    if (tid < 128) {
        int gr = base_row + tid;
        Sinv[tid] = (gr < n) ? __ldg(scale + gr) : 0.0f;
    }
    __syncthreads();

    int m_warp = (wid & 3) * 32;
    int n_warp = (wid >> 2) * 64;

    float acc[2][8][4];
#pragma unroll
    for (int i = 0; i < 2; i++)
#pragma unroll
        for (int j = 0; j < 8; j++)
#pragma unroll
            for (int k = 0; k < 4; k++) acc[i][j][k] = 0.0f;

    int g = lane >> 3, lr = lane & 7;
    int a_row = (g & 1) * 8 + lr;
    int a_col = (g >> 1) * 8;
    int b_row = a_row, b_col = a_col;

    for (int kc = 0; kc < 2; kc++) {
        if (kc) __syncthreads();
        const float* S = kc ? Aself : Aagg;

        // ---- A: 128 rows x 128 fp32 cols; split in-register -> AH/AL ----
#pragma unroll
        for (int i = 0; i < 16; i++) {
            int q = tid + i * 256;        // float4 slot, 0..4095 (32 per row)
            int row = q >> 5;
            int c4 = (q & 31) << 2;
            int gr = base_row + row;
            float4 v = (gr < n) ? __ldg((const float4*)(S + (size_t)gr * FD + c4))
                                : make_float4(0.f, 0.f, 0.f, 0.f);
            if (!kc) {
                float s = Sinv[row];
                v.x *= s; v.y *= s; v.z *= s; v.w *= s;
            }
            uint32_t h0, l0, h1, l1;
            split2(v.x, v.y, h0, l0);
            split2(v.z, v.w, h1, l1);
            uint32_t so = (uint32_t)(row * PS + c4) * 2;
            *(uint2*)(smem + OFF_AH + so) = make_uint2(h0, h1);
            *(uint2*)(smem + OFF_AL + so) = make_uint2(l0, l1);
        }
        // ---- W: 128 rows x 128 bf16 cols (hi+lo) ----
#pragma unroll
        for (int i = 0; i < 8; i++) {
            int q = tid + i * 256;        // uint4 slot, 0..2047 (16 per row)
            int row = q >> 4;
            int c8 = (q & 15) * 8;
            size_t gW = (size_t)row * 256 + kc * 128 + c8;
            uint32_t so = (uint32_t)(row * PS + c8) * 2;
            *(uint4*)(smem + OFF_WH + so) = *(const uint4*)(Whi + gW);
            *(uint4*)(smem + OFF_WL + so) = *(const uint4*)(Wlo + gW);
        }
        __syncthreads();

        // ---- compute ----
#pragma unroll
        for (int k16 = 0; k16 < 8; k16++) {
            int kb = k16 * 16;
            uint32_t ah[2][4], al[2][4];
#pragma unroll
            for (int mi = 0; mi < 2; mi++) {
                uint32_t ad = sb + (uint32_t)((m_warp + mi * 16 + a_row) * PS + kb + a_col) * 2;
                ldm_x4(ah[mi], OFF_AH + ad);
                ldm_x4(al[mi], OFF_AL + ad);
            }
            uint32_t bh[8][2], bl[8][2];
#pragma unroll
            for (int np = 0; np < 4; np++) {
                uint32_t bd = sb + (uint32_t)((n_warp + np * 16 + b_row) * PS + kb + b_col) * 2;
                uint32_t t[4];
                ldm_x4(t, OFF_WH + bd);
                bh[np * 2 + 0][0] = t[0]; bh[np * 2 + 0][1] = t[2];
                bh[np * 2 + 1][0] = t[1]; bh[np * 2 + 1][1] = t[3];
                ldm_x4(t, OFF_WL + bd);
                bl[np * 2 + 0][0] = t[0]; bl[np * 2 + 0][1] = t[2];
                bl[np * 2 + 1][0] = t[1]; bl[np * 2 + 1][1] = t[3];
            }
#pragma unroll
            for (int mi = 0; mi < 2; mi++)
#pragma unroll
                for (int ni = 0; ni < 8; ni++) {
                    mma_bf16(acc[mi][ni], ah[mi], bh[ni]);
                    mma_bf16(acc[mi][ni], ah[mi], bl[ni]);
                    mma_bf16(acc[mi][ni], al[mi], bh[ni]);
                }
        }
    }

    // ---- epilogue ----
    int r_in = lane >> 2;
    int c_in = (lane & 3) * 2;
#pragma unroll
    for (int mi = 0; mi < 2; mi++) {
#pragma unroll
        for (int half = 0; half < 2; half++) {
            int gr = base_row + m_warp + mi * 16 + r_in + half * 8;
            if (gr >= n) continue;
#pragma unroll
            for (int ni = 0; ni < 8; ni++) {
                int col = n_warp + ni * 8 + c_in;
                float y0 = acc[mi][ni][half * 2 + 0] + __ldg(bias + col + 0);
                float y1 = acc[mi][ni][half * 2 + 1] + __ldg(bias + col + 1);
                if (RELU) { y0 = fmaxf(y0, 0.f); y1 = fmaxf(y1, 0.f); }
                *(float2*)(outF + (size_t)gr * FD + col) = make_float2(y0, y1);
            }
        }
    }
}

// ---------------- launch ----------------------------------------------------
extern "C" void kernel_launch(void* const* d_in, const int* in_sizes, int n_in,
                              void* d_out, int out_size) {
    const float* x   = (const float*)d_in[0];
    const int*   ei  = (const int*)d_in[1];
    const float* W1l = (const float*)d_in[2];
    const float* b1l = (const float*)d_in[3];
    const float* W1r = (const float*)d_in[4];
    const float* W2l = (const float*)d_in[5];
    const float* b2l = (const float*)d_in[6];
    const float* W2r = (const float*)d_in[7];
    const float* W3l = (const float*)d_in[8];
    const float* b3l = (const float*)d_in[9];
    const float* W3r = (const float*)d_in[10];

    int n = in_sizes[0] / FD;
    int E = in_sizes[1] / 2;
    const int* src = ei;
    const int* dst = ei + E;

    float* out_h1 = (float*)d_out;
    float* out_h2 = (float*)d_out + (size_t)n * FD;

    void *pa1 = 0, *pa2 = 0, *px1 = 0, *pinv = 0, *pwh = 0, *pwl = 0;
    cudaGetSymbolAddress(&pa1, g_agg1);
    cudaGetSymbolAddress(&pa2, g_agg2);
    cudaGetSymbolAddress(&px1, g_x1);
    cudaGetSymbolAddress(&pinv, g_inv);
    cudaGetSymbolAddress(&pwh, g_wh);
    cudaGetSymbolAddress(&pwl, g_wl);
    float* agg1 = (float*)pa1;
    float* agg2 = (float*)pa2;
    float* x1   = (float*)px1;
    float* inv  = (float*)pinv;
    __nv_bfloat16* wh = (__nv_bfloat16*)pwh;
    __nv_bfloat16* wl = (__nv_bfloat16*)pwl;

    cudaFuncSetAttribute(gemm_mma<true>,  cudaFuncAttributeMaxDynamicSharedMemorySize, SMEM_TOTAL);
    cudaFuncSetAttribute(gemm_mma<false>, cudaFuncAttributeMaxDynamicSharedMemorySize, SMEM_TOTAL);

    int feat_total = n * FD;
    long long swarps = ((long long)E + 3) / 4;           // 4 edges per warp
    int sblocks = (int)((swarps * 32 + 255) / 256);
    int gblocks = (n + 127) / 128;

    zero_kernel<<<2048, 256>>>(feat_total, n);
    count_kernel<<<(E + 255) / 256, 256>>>(dst, E, n);
    inv_kernel<<<(n + 255) / 256, 256>>>(n);
    conv_w<<<(3 * 128 * 64 + 255) / 256, 256>>>(W1l, W1r, W2l, W2r, W3l, W3r);

    scatter_kernel<<<sblocks, 256>>>(x, src, dst, agg1, E, n);
    gemm_mma<true><<<gblocks, 256, SMEM_TOTAL>>>(agg1, inv, x, wh, wl, b1l, x1, n);

    scatter_kernel<<<sblocks, 256>>>(x1, src, dst, agg2, E, n);
    gemm_mma<false><<<gblocks, 256, SMEM_TOTAL>>>(agg2, inv, x1, wh + 32768, wl + 32768,
                                                  b2l, out_h1, n);
    gemm_mma<false><<<gblocks, 256, SMEM_TOTAL>>>(agg2, inv, x1, wh + 65536, wl + 65536,
                                                  b3l, out_h2, n);
}

// round 6
// speedup vs baseline: 2.6200x; 1.4725x over previous
#include <cuda_runtime.h>
#include <cuda_bf16.h>
#include <cstdint>

#define NMAX 50000
#define EMAX 800000
#define FD   128

// ---------------- scratch (device globals) ---------------------------------
__device__ float g_agg1[NMAX * FD];
__device__ float g_x1  [NMAX * FD];
__device__ float g_agg2[NMAX * FD];
__device__ int   g_cnti[NMAX];
__device__ int   g_off [NMAX + 1];
__device__ int   g_cur [NMAX];
__device__ int   g_part[256];
__device__ int   g_csr [EMAX];
// weights: 3 layers x [128 out x 256 k]  (k = [Wl | Wr]), bf16 hi/lo split
__device__ __nv_bfloat16 g_wh[3 * 128 * 256];
__device__ __nv_bfloat16 g_wl[3 * 128 * 256];

// ---------------- CSR build -------------------------------------------------
__global__ void zero_cnt(int n) {
    int i = blockIdx.x * blockDim.x + threadIdx.x;
    if (i < n) g_cnti[i] = 0;
}

__global__ void hist_kernel(const int* __restrict__ dst, int E, int n) {
    int e = blockIdx.x * blockDim.x + threadIdx.x;
    if (e < E) {
        int d = dst[e];
        if ((unsigned)d < (unsigned)n) atomicAdd(&g_cnti[d], 1);
    }
}

__global__ void part_kernel(int n) {          // block sums of 256-chunks
    __shared__ int buf[256];
    int i = blockIdx.x * 256 + threadIdx.x;
    buf[threadIdx.x] = (i < n) ? g_cnti[i] : 0;
    __syncthreads();
    for (int s = 128; s > 0; s >>= 1) {
        if (threadIdx.x < s) buf[threadIdx.x] += buf[threadIdx.x + s];
        __syncthreads();
    }
    if (threadIdx.x == 0) g_part[blockIdx.x] = buf[0];
}

__global__ void scan_part(int nblocks) {      // serial exclusive scan (tiny)
    if (threadIdx.x == 0 && blockIdx.x == 0) {
        int run = 0;
        for (int b = 0; b < nblocks; b++) {
            int t = g_part[b];
            g_part[b] = run;
            run += t;
        }
    }
}

__global__ void offsets_kernel(int n) {       // in-block exclusive scan + base
    __shared__ int buf[256];
    int tid = threadIdx.x;
    int i = blockIdx.x * 256 + tid;
    int c = (i < n) ? g_cnti[i] : 0;
    buf[tid] = c;
    __syncthreads();
    for (int s = 1; s < 256; s <<= 1) {
        int t = (tid >= s) ? buf[tid - s] : 0;
        __syncthreads();
        buf[tid] += t;
        __syncthreads();
    }
    int off = g_part[blockIdx.x] + buf[tid] - c;   // exclusive
    if (i < n) { g_off[i] = off; g_cur[i] = off; }
    if (i == n - 1) g_off[n] = off + c;
}

__global__ void fill_kernel(const int* __restrict__ src,
                            const int* __restrict__ dst, int E, int n) {
    int e = blockIdx.x * blockDim.x + threadIdx.x;
    if (e < E) {
        int d = dst[e], s = src[e];
        if ((unsigned)d < (unsigned)n && (unsigned)s < (unsigned)n) {
            int pos = atomicAdd(&g_cur[d], 1);
            g_csr[pos] = s;
        }
    }
}

// ---------------- gather aggregation (mean folded in) ------------------------
// one warp per dst node; MLP-4 unrolled neighbor loop; single write, no atomics
__global__ void gather_kernel(const float* __restrict__ feat,
                              float* __restrict__ agg, int n) {
    int gt = blockIdx.x * blockDim.x + threadIdx.x;
    int node = gt >> 5, lane = gt & 31;
    if (node >= n) return;
    int beg = __ldg(&g_off[node]);
    int end = __ldg(&g_off[node + 1]);
    float4 acc = make_float4(0.f, 0.f, 0.f, 0.f);
    int j = beg;
    for (; j + 4 <= end; j += 4) {
        int s0 = __ldg(&g_csr[j + 0]);
        int s1 = __ldg(&g_csr[j + 1]);
        int s2 = __ldg(&g_csr[j + 2]);
        int s3 = __ldg(&g_csr[j + 3]);
        float4 v0 = __ldg(((const float4*)(feat + (size_t)s0 * FD)) + lane);
        float4 v1 = __ldg(((const float4*)(feat + (size_t)s1 * FD)) + lane);
        float4 v2 = __ldg(((const float4*)(feat + (size_t)s2 * FD)) + lane);
        float4 v3 = __ldg(((const float4*)(feat + (size_t)s3 * FD)) + lane);
        acc.x += v0.x + v1.x + v2.x + v3.x;
        acc.y += v0.y + v1.y + v2.y + v3.y;
        acc.z += v0.z + v1.z + v2.z + v3.z;
        acc.w += v0.w + v1.w + v2.w + v3.w;
    }
    for (; j < end; j++) {
        int s = __ldg(&g_csr[j]);
        float4 v = __ldg(((const float4*)(feat + (size_t)s * FD)) + lane);
        acc.x += v.x; acc.y += v.y; acc.z += v.z; acc.w += v.w;
    }
    int deg = end - beg;
    float sc = (deg > 0) ? (1.0f / (float)deg) : 0.0f;
    acc.x *= sc; acc.y *= sc; acc.z *= sc; acc.w *= sc;
    *(((float4*)(agg + (size_t)node * FD)) + lane) = acc;
}

// ---------------- weight split ----------------------------------------------
__device__ __forceinline__ void split2(float a, float b, uint32_t& hi, uint32_t& lo) {
    __nv_bfloat16 ah = __float2bfloat16(a);
    __nv_bfloat16 bh = __float2bfloat16(b);
    __nv_bfloat162 h2 = __nv_bfloat162(ah, bh);
    __nv_bfloat162 l2 = __nv_bfloat162(__float2bfloat16(a - __bfloat162float(ah)),
                                       __float2bfloat16(b - __bfloat162float(bh)));
    hi = *(uint32_t*)&h2;
    lo = *(uint32_t*)&l2;
}

__device__ __forceinline__ void split_store(float v, __nv_bfloat16* h, __nv_bfloat16* l) {
    __nv_bfloat16 hb = __float2bfloat16(v);
    *h = hb;
    *l = __float2bfloat16(v - __bfloat162float(hb));
}

__global__ void conv_w(const float* W1l, const float* W1r,
                       const float* W2l, const float* W2r,
                       const float* W3l, const float* W3r) {
    int q = blockIdx.x * blockDim.x + threadIdx.x;
    if (q >= 3 * 128 * 64) return;
    int L = q / 8192, rem = q % 8192;
    int o = rem >> 6, kq = (rem & 63) << 2;
    const float* Wl = (L == 0) ? W1l : (L == 1) ? W2l : W3l;
    const float* Wr = (L == 0) ? W1r : (L == 1) ? W2r : W3r;
    const float* sp = (kq < 128) ? (Wl + o * 128 + kq) : (Wr + o * 128 + kq - 128);
    float4 v = __ldg((const float4*)sp);
    size_t out = (size_t)L * 32768 + (size_t)o * 256 + kq;
    split_store(v.x, g_wh + out + 0, g_wl + out + 0);
    split_store(v.y, g_wh + out + 1, g_wl + out + 1);
    split_store(v.z, g_wh + out + 2, g_wl + out + 2);
    split_store(v.w, g_wh + out + 3, g_wl + out + 3);
}

// ---------------- mma.sync bf16 GEMM ----------------------------------------
#define PS   136
#define BUFB (128 * PS * 2)

__device__ __forceinline__ uint32_t smem_u32(const void* p) {
    uint32_t a;
    asm("{ .reg .u64 t; cvta.to.shared.u64 t, %1; cvt.u32.u64 %0, t; }" : "=r"(a) : "l"(p));
    return a;
}

__device__ __forceinline__ void ldm_x4(uint32_t* r, uint32_t addr) {
    asm volatile("ldmatrix.sync.aligned.m8n8.x4.shared.b16 {%0,%1,%2,%3}, [%4];"
                 : "=r"(r[0]), "=r"(r[1]), "=r"(r[2]), "=r"(r[3]) : "r"(addr));
}

__device__ __forceinline__ void mma_bf16(float* d, const uint32_t* a, const uint32_t* b) {
    asm volatile("mma.sync.aligned.m16n8k16.row.col.f32.bf16.bf16.f32 "
                 "{%0,%1,%2,%3}, {%4,%5,%6,%7}, {%8,%9}, {%0,%1,%2,%3};"
                 : "+f"(d[0]), "+f"(d[1]), "+f"(d[2]), "+f"(d[3])
                 : "r"(a[0]), "r"(a[1]), "r"(a[2]), "r"(a[3]), "r"(b[0]), "r"(b[1]));
}

// ---- layer-1 GEMM: 256 threads, one output, relu ----
#define G1_AH 0
#define G1_AL (BUFB)
#define G1_WH (2 * BUFB)
#define G1_WL (3 * BUFB)
#define G1_SMEM (4 * BUFB)

__global__ void __launch_bounds__(256, 1)
gemm1(const float* __restrict__ Aagg, const float* __restrict__ Aself,
      const __nv_bfloat16* __restrict__ Whi, const __nv_bfloat16* __restrict__ Wlo,
      const float* __restrict__ bias, float* __restrict__ outF, int n) {
    extern __shared__ __align__(16) char smem[];
    uint32_t sb = smem_u32(smem);
    int tid = threadIdx.x, wid = tid >> 5, lane = tid & 31;
    int base_row = blockIdx.x * 128;

    int m_warp = (wid & 3) * 32;
    int n_warp = (wid >> 2) * 64;

    float acc[2][8][4];
#pragma unroll
    for (int i = 0; i < 2; i++)
#pragma unroll
        for (int j = 0; j < 8; j++)
#pragma unroll
            for (int k = 0; k < 4; k++) acc[i][j][k] = 0.0f;

    int g = lane >> 3, lr = lane & 7;
    int a_row = (g & 1) * 8 + lr;
    int a_col = (g >> 1) * 8;

    for (int kc = 0; kc < 2; kc++) {
        if (kc) __syncthreads();
        const float* S = kc ? Aself : Aagg;
#pragma unroll
        for (int i = 0; i < 16; i++) {
            int q = tid + i * 256;
            int row = q >> 5;
            int c4 = (q & 31) << 2;
            int gr = base_row + row;
            float4 v = (gr < n) ? __ldg((const float4*)(S + (size_t)gr * FD + c4))
                                : make_float4(0.f, 0.f, 0.f, 0.f);
            uint32_t h0, l0, h1, l1;
            split2(v.x, v.y, h0, l0);
            split2(v.z, v.w, h1, l1);
            uint32_t so = (uint32_t)(row * PS + c4) * 2;
            *(uint2*)(smem + G1_AH + so) = make_uint2(h0, h1);
            *(uint2*)(smem + G1_AL + so) = make_uint2(l0, l1);
        }
#pragma unroll
        for (int i = 0; i < 8; i++) {
            int q = tid + i * 256;
            int row = q >> 4;
            int c8 = (q & 15) * 8;
            size_t gW = (size_t)row * 256 + kc * 128 + c8;
            uint32_t so = (uint32_t)(row * PS + c8) * 2;
            *(uint4*)(smem + G1_WH + so) = *(const uint4*)(Whi + gW);
            *(uint4*)(smem + G1_WL + so) = *(const uint4*)(Wlo + gW);
        }
        __syncthreads();

#pragma unroll
        for (int k16 = 0; k16 < 8; k16++) {
            int kb = k16 * 16;
            uint32_t ah[2][4], al[2][4];
#pragma unroll
            for (int mi = 0; mi < 2; mi++) {
                uint32_t ad = sb + (uint32_t)((m_warp + mi * 16 + a_row) * PS + kb + a_col) * 2;
                ldm_x4(ah[mi], G1_AH + ad);
                ldm_x4(al[mi], G1_AL + ad);
            }
            uint32_t bh[8][2], bl[8][2];
#pragma unroll
            for (int np = 0; np < 4; np++) {
                uint32_t bd = sb + (uint32_t)((n_warp + np * 16 + a_row) * PS + kb + a_col) * 2;
                uint32_t t[4];
                ldm_x4(t, G1_WH + bd);
                bh[np * 2 + 0][0] = t[0]; bh[np * 2 + 0][1] = t[2];
                bh[np * 2 + 1][0] = t[1]; bh[np * 2 + 1][1] = t[3];
                ldm_x4(t, G1_WL + bd);
                bl[np * 2 + 0][0] = t[0]; bl[np * 2 + 0][1] = t[2];
                bl[np * 2 + 1][0] = t[1]; bl[np * 2 + 1][1] = t[3];
            }
#pragma unroll
            for (int mi = 0; mi < 2; mi++)
#pragma unroll
                for (int ni = 0; ni < 8; ni++) {
                    mma_bf16(acc[mi][ni], ah[mi], bh[ni]);
                    mma_bf16(acc[mi][ni], ah[mi], bl[ni]);
                    mma_bf16(acc[mi][ni], al[mi], bh[ni]);
                }
        }
    }

    int r_in = lane >> 2;
    int c_in = (lane & 3) * 2;
#pragma unroll
    for (int mi = 0; mi < 2; mi++)
#pragma unroll
        for (int half = 0; half < 2; half++) {
            int gr = base_row + m_warp + mi * 16 + r_in + half * 8;
            if (gr >= n) continue;
#pragma unroll
            for (int ni = 0; ni < 8; ni++) {
                int col = n_warp + ni * 8 + c_in;
                float y0 = fmaxf(acc[mi][ni][half * 2 + 0] + __ldg(bias + col + 0), 0.f);
                float y1 = fmaxf(acc[mi][ni][half * 2 + 1] + __ldg(bias + col + 1), 0.f);
                *(float2*)(outF + (size_t)gr * FD + col) = make_float2(y0, y1);
            }
        }
}

// ---- fused layers 2+3: 512 threads; warps 0-7 -> out1 (W2), 8-15 -> out2 (W3)
#define G2_AH 0
#define G2_AL (BUFB)
#define G2_W2H (2 * BUFB)
#define G2_W2L (3 * BUFB)
#define G2_W3H (4 * BUFB)
#define G2_W3L (5 * BUFB)
#define G2_SMEM (6 * BUFB)

__global__ void __launch_bounds__(512, 1)
gemm23(const float* __restrict__ Aagg, const float* __restrict__ Aself,
       const __nv_bfloat16* __restrict__ W2hi, const __nv_bfloat16* __restrict__ W2lo,
       const __nv_bfloat16* __restrict__ W3hi, const __nv_bfloat16* __restrict__ W3lo,
       const float* __restrict__ b2, const float* __restrict__ b3,
       float* __restrict__ out1, float* __restrict__ out2, int n) {
    extern __shared__ __align__(16) char smem[];
    uint32_t sb = smem_u32(smem);
    int tid = threadIdx.x, wid = tid >> 5, lane = tid & 31;
    int base_row = blockIdx.x * 128;

    int layer = wid >> 3;                 // 0 or 1
    int m_warp = (wid & 3) * 32;
    int n_warp = ((wid >> 2) & 1) * 64;
    uint32_t offWH = layer ? G2_W3H : G2_W2H;
    uint32_t offWL = layer ? G2_W3L : G2_W2L;

    float acc[2][8][4];
#pragma unroll
    for (int i = 0; i < 2; i++)
#pragma unroll
        for (int j = 0; j < 8; j++)
#pragma unroll
            for (int k = 0; k < 4; k++) acc[i][j][k] = 0.0f;

    int g = lane >> 3, lr = lane & 7;
    int a_row = (g & 1) * 8 + lr;
    int a_col = (g >> 1) * 8;

    for (int kc = 0; kc < 2; kc++) {
        if (kc) __syncthreads();
        const float* S = kc ? Aself : Aagg;
        // A: 4096 float4 slots over 512 threads = 8 iters
#pragma unroll
        for (int i = 0; i < 8; i++) {
            int q = tid + i * 512;
            int row = q >> 5;
            int c4 = (q & 31) << 2;
            int gr = base_row + row;
            float4 v = (gr < n) ? __ldg((const float4*)(S + (size_t)gr * FD + c4))
                                : make_float4(0.f, 0.f, 0.f, 0.f);
            uint32_t h0, l0, h1, l1;
            split2(v.x, v.y, h0, l0);
            split2(v.z, v.w, h1, l1);
            uint32_t so = (uint32_t)(row * PS + c4) * 2;
            *(uint2*)(smem + G2_AH + so) = make_uint2(h0, h1);
            *(uint2*)(smem + G2_AL + so) = make_uint2(l0, l1);
        }
        // W2 + W3: each 2048 uint4 slots over 512 threads = 4 iters each
#pragma unroll
        for (int i = 0; i < 4; i++) {
            int q = tid + i * 512;
            int row = q >> 4;
            int c8 = (q & 15) * 8;
            size_t gW = (size_t)row * 256 + kc * 128 + c8;
            uint32_t so = (uint32_t)(row * PS + c8) * 2;
            *(uint4*)(smem + G2_W2H + so) = *(const uint4*)(W2hi + gW);
            *(uint4*)(smem + G2_W2L + so) = *(const uint4*)(W2lo + gW);
            *(uint4*)(smem + G2_W3H + so) = *(const uint4*)(W3hi + gW);
            *(uint4*)(smem + G2_W3L + so) = *(const uint4*)(W3lo + gW);
        }
        __syncthreads();

#pragma unroll
        for (int k16 = 0; k16 < 8; k16++) {
            int kb = k16 * 16;
            uint32_t ah[2][4], al[2][4];
#pragma unroll
            for (int mi = 0; mi < 2; mi++) {
                uint32_t ad = sb + (uint32_t)((m_warp + mi * 16 + a_row) * PS + kb + a_col) * 2;
                ldm_x4(ah[mi], G2_AH + ad);
                ldm_x4(al[mi], G2_AL + ad);
            }
            uint32_t bh[8][2], bl[8][2];
#pragma unroll
            for (int np = 0; np < 4; np++) {
                uint32_t bd = sb + (uint32_t)((n_warp + np * 16 + a_row) * PS + kb + a_col) * 2;
                uint32_t t[4];
                ldm_x4(t, offWH + bd);
                bh[np * 2 + 0][0] = t[0]; bh[np * 2 + 0][1] = t[2];
                bh[np * 2 + 1][0] = t[1]; bh[np * 2 + 1][1] = t[3];
                ldm_x4(t, offWL + bd);
                bl[np * 2 + 0][0] = t[0]; bl[np * 2 + 0][1] = t[2];
                bl[np * 2 + 1][0] = t[1]; bl[np * 2 + 1][1] = t[3];
            }
#pragma unroll
            for (int mi = 0; mi < 2; mi++)
#pragma unroll
                for (int ni = 0; ni < 8; ni++) {
                    mma_bf16(acc[mi][ni], ah[mi], bh[ni]);
                    mma_bf16(acc[mi][ni], ah[mi], bl[ni]);
                    mma_bf16(acc[mi][ni], al[mi], bh[ni]);
                }
        }
    }

    const float* bias = layer ? b3 : b2;
    float* outF = layer ? out2 : out1;
    int r_in = lane >> 2;
    int c_in = (lane & 3) * 2;
#pragma unroll
    for (int mi = 0; mi < 2; mi++)
#pragma unroll
        for (int half = 0; half < 2; half++) {
            int gr = base_row + m_warp + mi * 16 + r_in + half * 8;
            if (gr >= n) continue;
#pragma unroll
            for (int ni = 0; ni < 8; ni++) {
                int col = n_warp + ni * 8 + c_in;
                float y0 = acc[mi][ni][half * 2 + 0] + __ldg(bias + col + 0);
                float y1 = acc[mi][ni][half * 2 + 1] + __ldg(bias + col + 1);
                *(float2*)(outF + (size_t)gr * FD + col) = make_float2(y0, y1);
            }
        }
}

// ---------------- launch ----------------------------------------------------
extern "C" void kernel_launch(void* const* d_in, const int* in_sizes, int n_in,
                              void* d_out, int out_size) {
    const float* x   = (const float*)d_in[0];
    const int*   ei  = (const int*)d_in[1];
    const float* W1l = (const float*)d_in[2];
    const float* b1l = (const float*)d_in[3];
    const float* W1r = (const float*)d_in[4];
    const float* W2l = (const float*)d_in[5];
    const float* b2l = (const float*)d_in[6];
    const float* W2r = (const float*)d_in[7];
    const float* W3l = (const float*)d_in[8];
    const float* b3l = (const float*)d_in[9];
    const float* W3r = (const float*)d_in[10];

    int n = in_sizes[0] / FD;
    int E = in_sizes[1] / 2;
    const int* src = ei;
    const int* dst = ei + E;

    float* out_h1 = (float*)d_out;
    float* out_h2 = (float*)d_out + (size_t)n * FD;

    void *pa1 = 0, *pa2 = 0, *px1 = 0, *pwh = 0, *pwl = 0;
    cudaGetSymbolAddress(&pa1, g_agg1);
    cudaGetSymbolAddress(&pa2, g_agg2);
    cudaGetSymbolAddress(&px1, g_x1);
    cudaGetSymbolAddress(&pwh, g_wh);
    cudaGetSymbolAddress(&pwl, g_wl);
    float* agg1 = (float*)pa1;
    float* agg2 = (float*)pa2;
    float* x1   = (float*)px1;
    __nv_bfloat16* wh = (__nv_bfloat16*)pwh;
    __nv_bfloat16* wl = (__nv_bfloat16*)pwl;

    cudaFuncSetAttribute(gemm1,  cudaFuncAttributeMaxDynamicSharedMemorySize, G1_SMEM);
    cudaFuncSetAttribute(gemm23, cudaFuncAttributeMaxDynamicSharedMemorySize, G2_SMEM);

    int nblocks256 = (n + 255) / 256;
    int eblocks = (E + 255) / 256;
    int gthreads = n * 32;
    int gabl = (gthreads + 255) / 256;
    int gblocks = (n + 127) / 128;

    // CSR build
    zero_cnt<<<nblocks256, 256>>>(n);
    hist_kernel<<<eblocks, 256>>>(dst, E, n);
    part_kernel<<<nblocks256, 256>>>(n);
    scan_part<<<1, 32>>>(nblocks256);
    offsets_kernel<<<nblocks256, 256>>>(n);
    fill_kernel<<<eblocks, 256>>>(src, dst, E, n);
    conv_w<<<(3 * 128 * 64 + 255) / 256, 256>>>(W1l, W1r, W2l, W2r, W3l, W3r);

    // layer 1
    gather_kernel<<<gabl, 256>>>(x, agg1, n);
    gemm1<<<gblocks, 256, G1_SMEM>>>(agg1, x, wh, wl, b1l, x1, n);

    // layers 2 + 3 (shared aggregation, fused GEMM)
    gather_kernel<<<gabl, 256>>>(x1, agg2, n);
    gemm23<<<gblocks, 512, G2_SMEM>>>(agg2, x1,
                                      wh + 32768, wl + 32768,
                                      wh + 65536, wl + 65536,
                                      b2l, b3l, out_h1, out_h2, n);
}